// round 1
// baseline (speedup 1.0000x reference)
#include <cuda_runtime.h>

#define NB 16
#define NT 8192
#define NE 64
#define NC 128
#define KSTR 129   // padded stride for transposed K tile (conflict-free staging)

// smem layout (floats):
//   KcT : [64][129]   transposed gathered K columns   (8256)
//   Vc  : [128][64]   gathered V columns, row-major   (8192)
//   qs  : [64][64]    Q rows * 1/sqrt(64)             (4096)
//   aT  : [8][128][4] per-warp A^T tile (4 rows)      (4096)
#define SM_FLOATS (64*KSTR + 128*64 + 64*64 + 8*128*4)
#define SM_BYTES  (SM_FLOATS * 4)

__device__ __forceinline__ float warpMax(float v) {
#pragma unroll
    for (int o = 16; o; o >>= 1) v = fmaxf(v, __shfl_xor_sync(0xffffffffu, v, o));
    return v;
}
__device__ __forceinline__ float warpSum(float v) {
#pragma unroll
    for (int o = 16; o; o >>= 1) v += __shfl_xor_sync(0xffffffffu, v, o);
    return v;
}

template<int KP>
__device__ __forceinline__ void process_pass(
    const float* __restrict__ KcT, const float* __restrict__ Vc,
    const float* __restrict__ qs, float* __restrict__ aTw,
    int r0, int lane, int i0, int c, int b,
    float* __restrict__ Outg, float* __restrict__ Ag, int writeA)
{
    // ---- QK: 4 rows x (32*KP) columns, dot over e=64 ----
    float s[4][KP];
#pragma unroll
    for (int r = 0; r < 4; ++r)
#pragma unroll
        for (int k = 0; k < KP; ++k) s[r][k] = 0.0f;

    for (int e = 0; e < 64; e += 4) {
        float4 q0 = *(const float4*)(qs + (r0 + 0) * NE + e);
        float4 q1 = *(const float4*)(qs + (r0 + 1) * NE + e);
        float4 q2 = *(const float4*)(qs + (r0 + 2) * NE + e);
        float4 q3 = *(const float4*)(qs + (r0 + 3) * NE + e);
        const float qa[4][4] = {
            {q0.x, q0.y, q0.z, q0.w},
            {q1.x, q1.y, q1.z, q1.w},
            {q2.x, q2.y, q2.z, q2.w},
            {q3.x, q3.y, q3.z, q3.w},
        };
#pragma unroll
        for (int ee = 0; ee < 4; ++ee) {
#pragma unroll
            for (int k = 0; k < KP; ++k) {
                float kv = KcT[(e + ee) * KSTR + lane + 32 * k];
                s[0][k] = fmaf(qa[0][ee], kv, s[0][k]);
                s[1][k] = fmaf(qa[1][ee], kv, s[1][k]);
                s[2][k] = fmaf(qa[2][ee], kv, s[2][k]);
                s[3][k] = fmaf(qa[3][ee], kv, s[3][k]);
            }
        }
    }

    // ---- mask + softmax per row ----
    float a[4][KP];
#pragma unroll
    for (int r = 0; r < 4; ++r) {
        const int i  = i0 + r0 + r;
        const int nv = (i + 1) >> 6;          // number of valid columns
        const bool emp = (nv == 0);           // fully-masked row -> zeros
        float m = -1e30f;
#pragma unroll
        for (int k = 0; k < KP; ++k) {
            const int j = lane + 32 * k;
            s[r][k] = (j < nv) ? s[r][k] : -1e30f;  // also kills garbage j >= c
            m = fmaxf(m, s[r][k]);
        }
        m = warpMax(m);
        float ls = 0.0f;
#pragma unroll
        for (int k = 0; k < KP; ++k) {
            float pz = __expf(s[r][k] - m);   // masked -> exp(-huge) = 0
            a[r][k] = pz;
            ls += pz;
        }
        ls = warpSum(ls);
        const float iv = 1.0f / ls;
#pragma unroll
        for (int k = 0; k < KP; ++k) a[r][k] = emp ? 0.0f : a[r][k] * iv;
    }

    // ---- stash A^T in smem for the AV pass (conflict-free STS.128) ----
#pragma unroll
    for (int k = 0; k < KP; ++k) {
        const int j = lane + 32 * k;
        float4 av = make_float4(a[0][k], a[1][k], a[2][k], a[3][k]);
        *(float4*)(aTw + j * 4) = av;
    }

    // ---- write A to global (all 128 cols; zeros beyond computed chunks) ----
    if (writeA) {
#pragma unroll
        for (int r = 0; r < 4; ++r) {
            const size_t base = ((size_t)(b * NT + i0 + r0 + r)) * NC + lane;
#pragma unroll
            for (int k = 0; k < 4; ++k)
                Ag[base + 32 * k] = (k < KP) ? a[r][k] : 0.0f;
        }
    }
    __syncwarp();

    // ---- AV: out[r][e] = sum_j a[r][j] * Vc[j][e]; lane owns e = 2l, 2l+1 ----
    float2 o0 = {0.f, 0.f}, o1 = {0.f, 0.f}, o2 = {0.f, 0.f}, o3 = {0.f, 0.f};
    const float* vbase = Vc + 2 * lane;
#pragma unroll 4
    for (int j = 0; j < c; ++j) {
        float4 av = *(const float4*)(aTw + j * 4);      // broadcast
        float2 v  = *(const float2*)(vbase + j * NE);
        o0.x = fmaf(av.x, v.x, o0.x); o0.y = fmaf(av.x, v.y, o0.y);
        o1.x = fmaf(av.y, v.x, o1.x); o1.y = fmaf(av.y, v.y, o1.y);
        o2.x = fmaf(av.z, v.x, o2.x); o2.y = fmaf(av.z, v.y, o2.y);
        o3.x = fmaf(av.w, v.x, o3.x); o3.y = fmaf(av.w, v.y, o3.y);
    }
    {
        const size_t ob = ((size_t)(b * NT + i0 + r0)) * NE + 2 * lane;
        *(float2*)(Outg + ob)          = o0;
        *(float2*)(Outg + ob + NE)     = o1;
        *(float2*)(Outg + ob + 2 * NE) = o2;
        *(float2*)(Outg + ob + 3 * NE) = o3;
    }
    __syncwarp();   // aTw reused by next pass
}

__global__ __launch_bounds__(256, 2)
void cba_kernel(const float* __restrict__ Qg, const float* __restrict__ Kg,
                const float* __restrict__ Vg, float* __restrict__ Outg,
                float* __restrict__ Ag, int writeA)
{
    extern __shared__ float smf[];
    float* KcT = smf;
    float* Vc  = KcT + 64 * KSTR;
    float* qs  = Vc + 128 * 64;
    float* aT  = qs + 64 * 64;

    const int rb   = 127 - (int)blockIdx.x;   // heavy tiles first
    const int b    = (int)blockIdx.y;
    const int c    = rb + 1;                  // columns this block can see
    const int KP   = (c + 31) >> 5;
    const int i0   = rb * 64;
    const int tid  = (int)threadIdx.x;
    const int w    = tid >> 5;
    const int lane = tid & 31;

    // ---- stage gathered K (transposed) and V columns ----
    for (int idx = tid; idx < c * 64; idx += 256) {
        const int j = idx >> 6, e = idx & 63;
        const size_t grow = ((size_t)(b * NT + 64 * j + 63)) * NE;
        KcT[e * KSTR + j] = Kg[grow + e];
        Vc[idx]           = Vg[grow + e];
    }
    // ---- stage Q rows, pre-scaled by 1/sqrt(64) ----
    {
        const size_t qbase = ((size_t)(b * NT + i0)) * NE;
        for (int idx = tid; idx < 64 * 64; idx += 256)
            qs[idx] = Qg[qbase + idx] * 0.125f;
    }
    __syncthreads();

    float* aTw = aT + w * NC * 4;
    const int rA = w * 8;       // this warp's first row (8 rows, two passes of 4)

    switch (KP) {
    case 1:
        process_pass<1>(KcT, Vc, qs, aTw, rA,     lane, i0, c, b, Outg, Ag, writeA);
        process_pass<1>(KcT, Vc, qs, aTw, rA + 4, lane, i0, c, b, Outg, Ag, writeA);
        break;
    case 2:
        process_pass<2>(KcT, Vc, qs, aTw, rA,     lane, i0, c, b, Outg, Ag, writeA);
        process_pass<2>(KcT, Vc, qs, aTw, rA + 4, lane, i0, c, b, Outg, Ag, writeA);
        break;
    case 3:
        process_pass<3>(KcT, Vc, qs, aTw, rA,     lane, i0, c, b, Outg, Ag, writeA);
        process_pass<3>(KcT, Vc, qs, aTw, rA + 4, lane, i0, c, b, Outg, Ag, writeA);
        break;
    default:
        process_pass<4>(KcT, Vc, qs, aTw, rA,     lane, i0, c, b, Outg, Ag, writeA);
        process_pass<4>(KcT, Vc, qs, aTw, rA + 4, lane, i0, c, b, Outg, Ag, writeA);
        break;
    }
}

extern "C" void kernel_launch(void* const* d_in, const int* in_sizes, int n_in,
                              void* d_out, int out_size)
{
    const float* Q = (const float*)d_in[0];
    const float* K = (const float*)d_in[1];
    const float* V = (const float*)d_in[2];
    float* Out = (float*)d_out;

    const int writeA = (out_size >= NB * NT * (NE + NC)) ? 1 : 0;
    float* A = Out + (size_t)NB * NT * NE;

    cudaFuncSetAttribute(cba_kernel, cudaFuncAttributeMaxDynamicSharedMemorySize, SM_BYTES);

    dim3 grid(128, NB);
    cba_kernel<<<grid, 256, SM_BYTES>>>(Q, K, V, Out, A, writeA);
}

// round 3
// speedup vs baseline: 2.0733x; 2.0733x over previous
#include <cuda_runtime.h>
#include <cuda_bf16.h>
#include <cstdint>

#define NB 16
#define NT 8192
#define NE 64
#define NC 128

// ---- smem layout (bytes) ----
#define QHI  0          // 128 x 72 bf16 (row stride 144B)
#define QLO  18432
#define KHI  36864      // 128 x 72 bf16  gathered K rows [j][e]
#define KLO  55296
#define VTHI 73728      // 64 x 136 bf16  V^T [e][j] (stride 272B)
#define VTLO 91136
#define SMEM_TOTAL 108544
#define QSTR 144
#define VSTR 272
#define DLO  18432      // QLO-QHI == KLO-KHI
#define DVLO 17408      // VTLO-VTHI

__device__ __forceinline__ uint32_t pk2(float a, float b) {
    __nv_bfloat162 t = __floats2bfloat162_rn(a, b);
    return *(uint32_t*)&t;
}
__device__ __forceinline__ float2 unpk2(uint32_t u) {
    __nv_bfloat162 t = *(__nv_bfloat162*)&u;
    return make_float2(__bfloat162float(t.x), __bfloat162float(t.y));
}

#define MMA16816(d0,d1,d2,d3,a0,a1,a2,a3,b0,b1)                              \
    asm volatile("mma.sync.aligned.m16n8k16.row.col.f32.bf16.bf16.f32 "      \
                 "{%0,%1,%2,%3}, {%4,%5,%6,%7}, {%8,%9}, {%0,%1,%2,%3};"     \
                 : "+f"(d0), "+f"(d1), "+f"(d2), "+f"(d3)                    \
                 : "r"(a0), "r"(a1), "r"(a2), "r"(a3), "r"(b0), "r"(b1))

template<int G>   // G = Np/16, Np = padded column count
__device__ __forceinline__ void warp_work(char* sm, int R, int lane, int i0,
                                          float* __restrict__ OutB,
                                          float* __restrict__ AB)
{
    const int g  = lane >> 2;
    const int tg = lane & 3;

    // ---- Q fragments (A operand of MMA1), held in regs ----
    uint32_t qh[4][4], ql[4][4];
    {
        const char* q0 = sm + QHI + (R + g) * QSTR + 4 * tg;
        const char* q8 = q0 + 8 * QSTR;
#pragma unroll
        for (int k = 0; k < 4; ++k) {
            qh[k][0] = *(const uint32_t*)(q0 + 32 * k);
            qh[k][1] = *(const uint32_t*)(q8 + 32 * k);
            qh[k][2] = *(const uint32_t*)(q0 + 32 * k + 16);
            qh[k][3] = *(const uint32_t*)(q8 + 32 * k + 16);
            ql[k][0] = *(const uint32_t*)(q0 + DLO + 32 * k);
            ql[k][1] = *(const uint32_t*)(q8 + DLO + 32 * k);
            ql[k][2] = *(const uint32_t*)(q0 + DLO + 32 * k + 16);
            ql[k][3] = *(const uint32_t*)(q8 + DLO + 32 * k + 16);
        }
    }

    const int i_lo = i0 + R + g;
    const int i_hi = i_lo + 8;
    const int nv_lo = (i_lo + 1) >> 6;
    const int nv_hi = (i_hi + 1) >> 6;

    // ---- MMA1 + exp, packed exp kept as MMA2 A-fragments ----
    uint32_t p01h[2 * G], p01l[2 * G], p23h[2 * G], p23l[2 * G];
    float sum_lo = 0.0f, sum_hi = 0.0f;

#pragma unroll
    for (int n = 0; n < 2 * G; ++n) {
        float d0 = 0.f, d1 = 0.f, d2 = 0.f, d3 = 0.f;
        const char* kb = sm + KHI + (8 * n + g) * QSTR + 4 * tg;
#pragma unroll
        for (int k = 0; k < 4; ++k) {
            uint32_t bh0 = *(const uint32_t*)(kb + 32 * k);
            uint32_t bh1 = *(const uint32_t*)(kb + 32 * k + 16);
            uint32_t bl0 = *(const uint32_t*)(kb + DLO + 32 * k);
            uint32_t bl1 = *(const uint32_t*)(kb + DLO + 32 * k + 16);
            MMA16816(d0, d1, d2, d3, qh[k][0], qh[k][1], qh[k][2], qh[k][3], bh0, bh1);
            MMA16816(d0, d1, d2, d3, qh[k][0], qh[k][1], qh[k][2], qh[k][3], bl0, bl1);
            MMA16816(d0, d1, d2, d3, ql[k][0], ql[k][1], ql[k][2], ql[k][3], bh0, bh1);
        }
        const int j0 = 8 * n + 2 * tg;
        float e0 = (j0     < nv_lo) ? __expf(d0) : 0.0f;
        float e1 = (j0 + 1 < nv_lo) ? __expf(d1) : 0.0f;
        float e2 = (j0     < nv_hi) ? __expf(d2) : 0.0f;
        float e3 = (j0 + 1 < nv_hi) ? __expf(d3) : 0.0f;
        sum_lo += e0 + e1;
        sum_hi += e2 + e3;
        p01h[n] = pk2(e0, e1); { float2 r = unpk2(p01h[n]); p01l[n] = pk2(e0 - r.x, e1 - r.y); }
        p23h[n] = pk2(e2, e3); { float2 r = unpk2(p23h[n]); p23l[n] = pk2(e2 - r.x, e3 - r.y); }
    }

    sum_lo += __shfl_xor_sync(0xffffffffu, sum_lo, 1);
    sum_lo += __shfl_xor_sync(0xffffffffu, sum_lo, 2);
    sum_hi += __shfl_xor_sync(0xffffffffu, sum_hi, 1);
    sum_hi += __shfl_xor_sync(0xffffffffu, sum_hi, 2);
    const float inv_lo = (nv_lo > 0) ? 1.0f / sum_lo : 0.0f;
    const float inv_hi = (nv_hi > 0) ? 1.0f / sum_hi : 0.0f;

    // ---- MMA2: Out = Ehat * V (A frags straight from exp regs) ----
    float o[8][4];
#pragma unroll
    for (int nt = 0; nt < 8; ++nt)
#pragma unroll
        for (int t = 0; t < 4; ++t) o[nt][t] = 0.0f;

#pragma unroll
    for (int kk = 0; kk < G; ++kk) {
        const uint32_t ah0 = p01h[2 * kk], ah1 = p23h[2 * kk];
        const uint32_t ah2 = p01h[2 * kk + 1], ah3 = p23h[2 * kk + 1];
        const uint32_t al0 = p01l[2 * kk], al1 = p23l[2 * kk];
        const uint32_t al2 = p01l[2 * kk + 1], al3 = p23l[2 * kk + 1];
#pragma unroll
        for (int nt = 0; nt < 8; ++nt) {
            const char* vp = sm + VTHI + (8 * nt + g) * VSTR + (16 * kk + 2 * tg) * 2;
            uint32_t bh0 = *(const uint32_t*)(vp);
            uint32_t bh1 = *(const uint32_t*)(vp + 16);
            uint32_t bl0 = *(const uint32_t*)(vp + DVLO);
            uint32_t bl1 = *(const uint32_t*)(vp + DVLO + 16);
            MMA16816(o[nt][0], o[nt][1], o[nt][2], o[nt][3], ah0, ah1, ah2, ah3, bh0, bh1);
            MMA16816(o[nt][0], o[nt][1], o[nt][2], o[nt][3], ah0, ah1, ah2, ah3, bl0, bl1);
            MMA16816(o[nt][0], o[nt][1], o[nt][2], o[nt][3], al0, al1, al2, al3, bh0, bh1);
        }
    }

    // ---- write Out (normalized) ----
#pragma unroll
    for (int nt = 0; nt < 8; ++nt) {
        const int e = 8 * nt + 2 * tg;
        *(float2*)(OutB + (size_t)(R + g) * NE + e)     = make_float2(o[nt][0] * inv_lo, o[nt][1] * inv_lo);
        *(float2*)(OutB + (size_t)(R + g + 8) * NE + e) = make_float2(o[nt][2] * inv_hi, o[nt][3] * inv_hi);
    }

    // ---- write A (normalized, reconstructed hi+lo) ----
#pragma unroll
    for (int n = 0; n < 2 * G; ++n) {
        const int j = 8 * n + 2 * tg;
        float2 h = unpk2(p01h[n]), l = unpk2(p01l[n]);
        *(float2*)(AB + (size_t)(R + g) * NC + j) =
            make_float2((h.x + l.x) * inv_lo, (h.y + l.y) * inv_lo);
        h = unpk2(p23h[n]); l = unpk2(p23l[n]);
        *(float2*)(AB + (size_t)(R + g + 8) * NC + j) =
            make_float2((h.x + l.x) * inv_hi, (h.y + l.y) * inv_hi);
    }

    // ---- zero tail columns [16G, 128) of A ----
    if (G < 8) {
        const int Np = 16 * G;
        const int t4 = (NC - Np) >> 2;          // float4s per row
        for (int t = lane; t < 16 * t4; t += 32) {
            const int row = t / t4, cq = t - row * t4;
            *(float4*)(AB + (size_t)(R + row) * NC + Np + 4 * cq) =
                make_float4(0.f, 0.f, 0.f, 0.f);
        }
    }
}

__global__ __launch_bounds__(256, 2)
void cba_mma(const float* __restrict__ Qg, const float* __restrict__ Kg,
             const float* __restrict__ Vg, float* __restrict__ Outg,
             float* __restrict__ Ag)
{
    extern __shared__ char sm[];
    const int tid  = (int)threadIdx.x;
    const int lane = tid & 31;
    const int w    = tid >> 5;
    const int p    = 63 - (int)blockIdx.x;    // heavy tiles first
    const int b    = (int)blockIdx.y;
    const int c    = 2 * p + 2;
    const int G    = (c + 15) >> 4;
    const int Np   = G << 4;
    const int i0   = p << 7;

    // ---- stage Q (prescaled 1/8) as bf16 hi/lo [r][e] ----
    {
        const float* Qb = Qg + (size_t)(b * NT + i0) * NE;
        for (int idx = tid; idx < 128 * 16; idx += 256) {
            const int rr = idx >> 4, e4 = (idx & 15) << 2;
            float4 q = *(const float4*)(Qb + (size_t)rr * NE + e4);
            q.x *= 0.125f; q.y *= 0.125f; q.z *= 0.125f; q.w *= 0.125f;
            const uint32_t h01 = pk2(q.x, q.y), h23 = pk2(q.z, q.w);
            float2 r01 = unpk2(h01), r23 = unpk2(h23);
            const uint32_t l01 = pk2(q.x - r01.x, q.y - r01.y);
            const uint32_t l23 = pk2(q.z - r23.x, q.w - r23.y);
            char* dst = sm + QHI + rr * QSTR + e4 * 2;
            *(uint2*)dst         = make_uint2(h01, h23);
            *(uint2*)(dst + DLO) = make_uint2(l01, l23);
        }
    }
    // ---- stage gathered K rows [j][e] ----
    {
        const float* Kb = Kg + (size_t)b * NT * NE + (size_t)63 * NE;
        for (int idx = tid; idx < c * 16; idx += 256) {
            const int j = idx >> 4, e4 = (idx & 15) << 2;
            const float4 k = *(const float4*)(Kb + (size_t)j * 64 * NE + e4);
            const uint32_t h01 = pk2(k.x, k.y), h23 = pk2(k.z, k.w);
            float2 r01 = unpk2(h01), r23 = unpk2(h23);
            const uint32_t l01 = pk2(k.x - r01.x, k.y - r01.y);
            const uint32_t l23 = pk2(k.z - r23.x, k.w - r23.y);
            char* dst = sm + KHI + j * QSTR + e4 * 2;
            *(uint2*)dst         = make_uint2(h01, h23);
            *(uint2*)(dst + DLO) = make_uint2(l01, l23);
        }
    }
    // ---- stage gathered V as V^T [e][j] ----
    {
        const float* Vb = Vg + (size_t)b * NT * NE + (size_t)63 * NE;
        for (int idx = tid; idx < c * 16; idx += 256) {
            const int j = idx >> 4, e4 = (idx & 15) << 2;
            const float4 v = *(const float4*)(Vb + (size_t)j * 64 * NE + e4);
            const float vv[4] = {v.x, v.y, v.z, v.w};
#pragma unroll
            for (int t = 0; t < 4; ++t) {
                const int e = e4 + t;
                const __nv_bfloat16 h = __float2bfloat16(vv[t]);
                const __nv_bfloat16 l = __float2bfloat16(vv[t] - __bfloat162float(h));
                char* dst = sm + VTHI + e * VSTR + j * 2;
                *(__nv_bfloat16*)dst          = h;
                *(__nv_bfloat16*)(dst + DVLO) = l;
            }
        }
        // zero V^T pad columns [c, Np) — garbage here would hit MMA2
        const int pad = Np - c;
        if (pad > 0) {
            for (int idx = tid; idx < 64 * pad; idx += 256) {
                const int e = idx / pad, j = c + (idx - e * pad);
                char* dst = sm + VTHI + e * VSTR + j * 2;
                *(__nv_bfloat16*)dst          = __ushort_as_bfloat16(0);
                *(__nv_bfloat16*)(dst + DVLO) = __ushort_as_bfloat16(0);
            }
        }
    }
    __syncthreads();

    float* OutB = Outg + (size_t)(b * NT + i0) * NE;
    float* AB   = Ag   + (size_t)(b * NT + i0) * NC;
    const int R = w << 4;

    switch (G) {
    case 1: warp_work<1>(sm, R, lane, i0, OutB, AB); break;
    case 2: warp_work<2>(sm, R, lane, i0, OutB, AB); break;
    case 3: warp_work<3>(sm, R, lane, i0, OutB, AB); break;
    case 4: warp_work<4>(sm, R, lane, i0, OutB, AB); break;
    case 5: warp_work<5>(sm, R, lane, i0, OutB, AB); break;
    case 6: warp_work<6>(sm, R, lane, i0, OutB, AB); break;
    case 7: warp_work<7>(sm, R, lane, i0, OutB, AB); break;
    default: warp_work<8>(sm, R, lane, i0, OutB, AB); break;
    }
}

extern "C" void kernel_launch(void* const* d_in, const int* in_sizes, int n_in,
                              void* d_out, int out_size)
{
    const float* Q = (const float*)d_in[0];
    const float* K = (const float*)d_in[1];
    const float* V = (const float*)d_in[2];
    float* Out = (float*)d_out;
    float* A   = Out + (size_t)NB * NT * NE;

    cudaFuncSetAttribute(cba_mma, cudaFuncAttributeMaxDynamicSharedMemorySize, SMEM_TOTAL);
    dim3 grid(64, NB);
    cba_mma<<<grid, 256, SMEM_TOTAL>>>(Q, K, V, Out, A);
}

// round 4
// speedup vs baseline: 2.7585x; 1.3305x over previous
#include <cuda_runtime.h>
#include <cuda_bf16.h>
#include <cstdint>

#define NB 16
#define NT 8192
#define NE 64
#define NC 128

// ---- smem layout: K and V stored row-major [j][e], bf16 hi/lo, stride 144B ----
#define STR  144
#define KHI  0
#define KLO  18432
#define VHI  36864
#define VLO  55296
#define DLO  18432          // hi->lo delta (same for K and V)
#define SMEM_TOTAL 73728

__device__ __forceinline__ uint32_t smem_u32(const void* p) {
    uint32_t a;
    asm("{ .reg .u64 t; cvta.to.shared.u64 t, %1; cvt.u32.u64 %0, t; }" : "=r"(a) : "l"(p));
    return a;
}
__device__ __forceinline__ uint32_t pk2(float a, float b) {
    __nv_bfloat162 t = __floats2bfloat162_rn(a, b);
    return *(uint32_t*)&t;
}
__device__ __forceinline__ float2 unpk2(uint32_t u) {
    __nv_bfloat162 t = *(__nv_bfloat162*)&u;
    return make_float2(__bfloat162float(t.x), __bfloat162float(t.y));
}

#define MMA16816(d0,d1,d2,d3,a0,a1,a2,a3,b0,b1)                              \
    asm volatile("mma.sync.aligned.m16n8k16.row.col.f32.bf16.bf16.f32 "      \
                 "{%0,%1,%2,%3}, {%4,%5,%6,%7}, {%8,%9}, {%0,%1,%2,%3};"     \
                 : "+f"(d0), "+f"(d1), "+f"(d2), "+f"(d3)                    \
                 : "r"(a0), "r"(a1), "r"(a2), "r"(a3), "r"(b0), "r"(b1))

#define LDSM4(r0,r1,r2,r3,addr)                                              \
    asm volatile("ldmatrix.sync.aligned.m8n8.x4.shared.b16 {%0,%1,%2,%3}, [%4];" \
                 : "=r"(r0), "=r"(r1), "=r"(r2), "=r"(r3) : "r"(addr))

#define LDSM4T(r0,r1,r2,r3,addr)                                             \
    asm volatile("ldmatrix.sync.aligned.m8n8.x4.trans.shared.b16 {%0,%1,%2,%3}, [%4];" \
                 : "=r"(r0), "=r"(r1), "=r"(r2), "=r"(r3) : "r"(addr))

template<int G>   // G = Np/16
__device__ __forceinline__ void warp_work(uint32_t smb, int R, int lane, int i0,
                                          const uint32_t qh[4][4], const uint32_t ql[4][4],
                                          float* __restrict__ OutB, float* __restrict__ AB)
{
    const int g  = lane >> 2;
    const int tg = lane & 3;
    const int nv_lo = (i0 + R + g + 1) >> 6;
    const int nv_hi = (i0 + R + g + 8 + 1) >> 6;

    // per-lane ldmatrix base addresses
    const uint32_t ka = smb + KHI + (uint32_t)((lane & 7) * STR + (lane >> 3) * 16);
    const uint32_t va = smb + VHI +
        (uint32_t)(((lane & 7) + ((lane >> 3) & 1) * 8) * STR + (lane >> 4) * 16);

    uint32_t p01h[2 * G], p01l[2 * G], p23h[2 * G], p23l[2 * G];
    float sum_lo = 0.0f, sum_hi = 0.0f;

    // ---- MMA1: 3 independent 4-chains per n-tile ----
#pragma unroll
    for (int n = 0; n < 2 * G; ++n) {
        const uint32_t kan = ka + (uint32_t)(n * 8 * STR);
        uint32_t kh[8], kl[8];
        LDSM4(kh[0], kh[1], kh[2], kh[3], kan);
        LDSM4(kh[4], kh[5], kh[6], kh[7], kan + 64);
        LDSM4(kl[0], kl[1], kl[2], kl[3], kan + DLO);
        LDSM4(kl[4], kl[5], kl[6], kl[7], kan + DLO + 64);

        float dA[4] = {0.f, 0.f, 0.f, 0.f};
        float dB[4] = {0.f, 0.f, 0.f, 0.f};
        float dC[4] = {0.f, 0.f, 0.f, 0.f};
#pragma unroll
        for (int k = 0; k < 4; ++k)
            MMA16816(dA[0], dA[1], dA[2], dA[3],
                     qh[k][0], qh[k][1], qh[k][2], qh[k][3], kh[2 * k], kh[2 * k + 1]);
#pragma unroll
        for (int k = 0; k < 4; ++k)
            MMA16816(dB[0], dB[1], dB[2], dB[3],
                     qh[k][0], qh[k][1], qh[k][2], qh[k][3], kl[2 * k], kl[2 * k + 1]);
#pragma unroll
        for (int k = 0; k < 4; ++k)
            MMA16816(dC[0], dC[1], dC[2], dC[3],
                     ql[k][0], ql[k][1], ql[k][2], ql[k][3], kh[2 * k], kh[2 * k + 1]);

        const float d0 = dA[0] + dB[0] + dC[0];
        const float d1 = dA[1] + dB[1] + dC[1];
        const float d2 = dA[2] + dB[2] + dC[2];
        const float d3 = dA[3] + dB[3] + dC[3];

        const int j0 = 8 * n + 2 * tg;
        const float e0 = (j0     < nv_lo) ? __expf(d0) : 0.0f;
        const float e1 = (j0 + 1 < nv_lo) ? __expf(d1) : 0.0f;
        const float e2 = (j0     < nv_hi) ? __expf(d2) : 0.0f;
        const float e3 = (j0 + 1 < nv_hi) ? __expf(d3) : 0.0f;
        sum_lo += e0 + e1;
        sum_hi += e2 + e3;
        p01h[n] = pk2(e0, e1); { float2 r = unpk2(p01h[n]); p01l[n] = pk2(e0 - r.x, e1 - r.y); }
        p23h[n] = pk2(e2, e3); { float2 r = unpk2(p23h[n]); p23l[n] = pk2(e2 - r.x, e3 - r.y); }
    }

    sum_lo += __shfl_xor_sync(0xffffffffu, sum_lo, 1);
    sum_lo += __shfl_xor_sync(0xffffffffu, sum_lo, 2);
    sum_hi += __shfl_xor_sync(0xffffffffu, sum_hi, 1);
    sum_hi += __shfl_xor_sync(0xffffffffu, sum_hi, 2);
    const float inv_lo = (nv_lo > 0) ? 1.0f / sum_lo : 0.0f;
    const float inv_hi = (nv_hi > 0) ? 1.0f / sum_hi : 0.0f;

    // ---- MMA2: Out = Ehat * V (V frags via ldmatrix.trans) ----
    float o[8][4];
#pragma unroll
    for (int nt = 0; nt < 8; ++nt)
#pragma unroll
        for (int t = 0; t < 4; ++t) o[nt][t] = 0.0f;

#pragma unroll
    for (int kk = 0; kk < G; ++kk) {
        const uint32_t ah0 = p01h[2 * kk], ah1 = p23h[2 * kk];
        const uint32_t ah2 = p01h[2 * kk + 1], ah3 = p23h[2 * kk + 1];
        const uint32_t al0 = p01l[2 * kk], al1 = p23l[2 * kk];
        const uint32_t al2 = p01l[2 * kk + 1], al3 = p23l[2 * kk + 1];
        const uint32_t vak = va + (uint32_t)(kk * 16 * STR);

        uint32_t vh[16];
        LDSM4T(vh[0],  vh[1],  vh[2],  vh[3],  vak);
        LDSM4T(vh[4],  vh[5],  vh[6],  vh[7],  vak + 32);
        LDSM4T(vh[8],  vh[9],  vh[10], vh[11], vak + 64);
        LDSM4T(vh[12], vh[13], vh[14], vh[15], vak + 96);
#pragma unroll
        for (int nt = 0; nt < 8; ++nt) {
            const uint32_t b0 = vh[(nt >> 1) * 4 + (nt & 1) * 2];
            const uint32_t b1 = vh[(nt >> 1) * 4 + (nt & 1) * 2 + 1];
            MMA16816(o[nt][0], o[nt][1], o[nt][2], o[nt][3], ah0, ah1, ah2, ah3, b0, b1);
        }
#pragma unroll
        for (int nt = 0; nt < 8; ++nt) {
            const uint32_t b0 = vh[(nt >> 1) * 4 + (nt & 1) * 2];
            const uint32_t b1 = vh[(nt >> 1) * 4 + (nt & 1) * 2 + 1];
            MMA16816(o[nt][0], o[nt][1], o[nt][2], o[nt][3], al0, al1, al2, al3, b0, b1);
        }
        uint32_t vl[16];
        LDSM4T(vl[0],  vl[1],  vl[2],  vl[3],  vak + DLO);
        LDSM4T(vl[4],  vl[5],  vl[6],  vl[7],  vak + DLO + 32);
        LDSM4T(vl[8],  vl[9],  vl[10], vl[11], vak + DLO + 64);
        LDSM4T(vl[12], vl[13], vl[14], vl[15], vak + DLO + 96);
#pragma unroll
        for (int nt = 0; nt < 8; ++nt) {
            const uint32_t b0 = vl[(nt >> 1) * 4 + (nt & 1) * 2];
            const uint32_t b1 = vl[(nt >> 1) * 4 + (nt & 1) * 2 + 1];
            MMA16816(o[nt][0], o[nt][1], o[nt][2], o[nt][3], ah0, ah1, ah2, ah3, b0, b1);
        }
    }

    // ---- write Out (normalized) ----
#pragma unroll
    for (int nt = 0; nt < 8; ++nt) {
        const int e = 8 * nt + 2 * tg;
        *(float2*)(OutB + (size_t)(R + g) * NE + e)     = make_float2(o[nt][0] * inv_lo, o[nt][1] * inv_lo);
        *(float2*)(OutB + (size_t)(R + g + 8) * NE + e) = make_float2(o[nt][2] * inv_hi, o[nt][3] * inv_hi);
    }
    // ---- write A (normalized, hi+lo reconstructed) ----
#pragma unroll
    for (int n = 0; n < 2 * G; ++n) {
        const int j = 8 * n + 2 * tg;
        float2 h = unpk2(p01h[n]), l = unpk2(p01l[n]);
        *(float2*)(AB + (size_t)(R + g) * NC + j) =
            make_float2((h.x + l.x) * inv_lo, (h.y + l.y) * inv_lo);
        h = unpk2(p23h[n]); l = unpk2(p23l[n]);
        *(float2*)(AB + (size_t)(R + g + 8) * NC + j) =
            make_float2((h.x + l.x) * inv_hi, (h.y + l.y) * inv_hi);
    }
    // ---- zero tail columns [16G, 128) of A ----
    if (G < 8) {
        const int Np = 16 * G;
        const int t4 = (NC - Np) >> 2;
        for (int t = lane; t < 16 * t4; t += 32) {
            const int row = t / t4, cq = t - row * t4;
            *(float4*)(AB + (size_t)(R + row) * NC + Np + 4 * cq) =
                make_float4(0.f, 0.f, 0.f, 0.f);
        }
    }
}

__global__ __launch_bounds__(256, 2)
void cba_mma(const float* __restrict__ Qg, const float* __restrict__ Kg,
             const float* __restrict__ Vg, float* __restrict__ Outg,
             float* __restrict__ Ag)
{
    extern __shared__ char sm[];
    const int tid  = (int)threadIdx.x;
    const int lane = tid & 31;
    const int w    = tid >> 5;
    const int p    = 63 - (int)blockIdx.x;
    const int b    = (int)blockIdx.y;
    const int c    = 2 * p + 2;
    const int G    = (c + 15) >> 4;
    const int Np   = G << 4;
    const int i0   = p << 7;
    const int g    = lane >> 2;
    const int tg   = lane & 3;
    const int R    = w << 4;
    const uint32_t smb = smem_u32(sm);

    // ---- issue Q fragment loads early (latency hidden behind K/V staging) ----
    float2 qf[4][4];
    {
        const float* Qb = Qg + (size_t)(b * NT + i0) * NE;
#pragma unroll
        for (int k = 0; k < 4; ++k) {
            const float* q0 = Qb + (size_t)(R + g) * NE + 16 * k + 2 * tg;
            const float* q8 = q0 + 8 * NE;
            qf[k][0] = *(const float2*)q0;
            qf[k][1] = *(const float2*)q8;
            qf[k][2] = *(const float2*)(q0 + 8);
            qf[k][3] = *(const float2*)(q8 + 8);
        }
    }

    // ---- stage gathered K and V rows [j][e], bf16 hi/lo ----
    {
        const float* Kb = Kg + (size_t)b * NT * NE + (size_t)63 * NE;
        const float* Vb = Vg + (size_t)b * NT * NE + (size_t)63 * NE;
        for (int idx = tid; idx < c * 16; idx += 256) {
            const int j = idx >> 4, e4 = (idx & 15) << 2;
            const size_t goff = (size_t)j * 64 * NE + e4;
            {
                const float4 k4 = *(const float4*)(Kb + goff);
                const uint32_t h01 = pk2(k4.x, k4.y), h23 = pk2(k4.z, k4.w);
                float2 r01 = unpk2(h01), r23 = unpk2(h23);
                const uint32_t l01 = pk2(k4.x - r01.x, k4.y - r01.y);
                const uint32_t l23 = pk2(k4.z - r23.x, k4.w - r23.y);
                char* dst = sm + KHI + j * STR + e4 * 2;
                *(uint2*)dst         = make_uint2(h01, h23);
                *(uint2*)(dst + DLO) = make_uint2(l01, l23);
            }
            {
                const float4 v4 = *(const float4*)(Vb + goff);
                const uint32_t h01 = pk2(v4.x, v4.y), h23 = pk2(v4.z, v4.w);
                float2 r01 = unpk2(h01), r23 = unpk2(h23);
                const uint32_t l01 = pk2(v4.x - r01.x, v4.y - r01.y);
                const uint32_t l23 = pk2(v4.z - r23.x, v4.w - r23.y);
                char* dst = sm + VHI + j * STR + e4 * 2;
                *(uint2*)dst         = make_uint2(h01, h23);
                *(uint2*)(dst + DLO) = make_uint2(l01, l23);
            }
        }
        // zero pad rows j in [c, Np) for both K and V
        for (int idx = tid; idx < (Np - c) * 16; idx += 256) {
            const int j = c + (idx >> 4), e4 = (idx & 15) << 2;
            char* dk = sm + KHI + j * STR + e4 * 2;
            char* dv = sm + VHI + j * STR + e4 * 2;
            *(uint2*)dk         = make_uint2(0u, 0u);
            *(uint2*)(dk + DLO) = make_uint2(0u, 0u);
            *(uint2*)dv         = make_uint2(0u, 0u);
            *(uint2*)(dv + DLO) = make_uint2(0u, 0u);
        }
    }

    // ---- convert Q to bf16 hi/lo fragments (overlaps other warps' staging) ----
    uint32_t qh[4][4], ql[4][4];
#pragma unroll
    for (int k = 0; k < 4; ++k)
#pragma unroll
        for (int t = 0; t < 4; ++t) {
            const float x = qf[k][t].x * 0.125f, y = qf[k][t].y * 0.125f;
            qh[k][t] = pk2(x, y);
            float2 r = unpk2(qh[k][t]);
            ql[k][t] = pk2(x - r.x, y - r.y);
        }

    __syncthreads();

    float* OutB = Outg + (size_t)(b * NT + i0) * NE;
    float* AB   = Ag   + (size_t)(b * NT + i0) * NC;

    switch (G) {
    case 1: warp_work<1>(smb, R, lane, i0, qh, ql, OutB, AB); break;
    case 2: warp_work<2>(smb, R, lane, i0, qh, ql, OutB, AB); break;
    case 3: warp_work<3>(smb, R, lane, i0, qh, ql, OutB, AB); break;
    case 4: warp_work<4>(smb, R, lane, i0, qh, ql, OutB, AB); break;
    case 5: warp_work<5>(smb, R, lane, i0, qh, ql, OutB, AB); break;
    case 6: warp_work<6>(smb, R, lane, i0, qh, ql, OutB, AB); break;
    case 7: warp_work<7>(smb, R, lane, i0, qh, ql, OutB, AB); break;
    default: warp_work<8>(smb, R, lane, i0, qh, ql, OutB, AB); break;
    }
}

extern "C" void kernel_launch(void* const* d_in, const int* in_sizes, int n_in,
                              void* d_out, int out_size)
{
    const float* Q = (const float*)d_in[0];
    const float* K = (const float*)d_in[1];
    const float* V = (const float*)d_in[2];
    float* Out = (float*)d_out;
    float* A   = Out + (size_t)NB * NT * NE;

    cudaFuncSetAttribute(cba_mma, cudaFuncAttributeMaxDynamicSharedMemorySize, SMEM_TOTAL);
    dim3 grid(64, NB);
    cba_mma<<<grid, 256, SMEM_TOTAL>>>(Q, K, V, Out, A);
}